// round 3
// baseline (speedup 1.0000x reference)
#include <cuda_runtime.h>

#define THRESH 0.5f
#define ALPHA  0.1f

// B=64, N=16384, C=16 -> 1,048,576 rows of 16 floats each.
// 4 threads cooperate on one row; each thread loads one float4 (16B),
// so every warp-level LDG.128 covers 512 fully-contiguous bytes.

static constexpr int C = 16;
static constexpr int THREADS = 256;
static constexpr int BLOCKS = 148 * 8;  // grid-stride; fine for 148 or 152 SMs

__global__ void mloss_init(float* out) {
    out[0] = 0.0f;
}

__device__ __forceinline__ float slot_contrib(
    const float* __restrict__ x, const float* __restrict__ y, int slot)
{
    const int row = slot >> 2;
    const int q = slot & 3;
    const int base = row * C + q * 4;   // max ~16.7M, fits int

    const float4 xv = *reinterpret_cast<const float4*>(x + base);
    const float4 yv = *reinterpret_cast<const float4*>(y + base);

    float d0 = yv.x - xv.x;
    float d1 = yv.y - xv.y;
    float d2 = yv.z - xv.z;
    float d3 = yv.w - xv.w;
    float sq = d0 * d0 + d1 * d1 + d2 * d2 + d3 * d3;

    // sum the 4 quarter-partials across the 4-lane group
    sq += __shfl_xor_sync(0xFFFFFFFFu, sq, 1);
    sq += __shfl_xor_sync(0xFFFFFFFFu, sq, 2);

    // lane with q==0 holds x[...,0] (xv.x) and y[...,0] (yv.x)
    if (q == 0) {
        return (yv.x > THRESH) ? sq : (ALPHA * xv.x * xv.x);
    }
    return 0.0f;
}

__global__ __launch_bounds__(THREADS) void mloss_kernel(
    const float* __restrict__ x,
    const float* __restrict__ y,
    float* __restrict__ out,
    int n_slots)
{
    const int g0 = blockIdx.x * blockDim.x + threadIdx.x;
    const int stride = gridDim.x * blockDim.x;

    float acc = 0.0f;

    // Unroll x2: two independent row-slots in flight -> 4 outstanding
    // float4 loads per thread, hiding DRAM latency.
    int slot = g0;
    for (; slot + stride < n_slots; slot += 2 * stride) {
        acc += slot_contrib(x, y, slot);
        acc += slot_contrib(x, y, slot + stride);
    }
    if (slot < n_slots) {
        acc += slot_contrib(x, y, slot);
    }

    // ---- block reduction ----
    #pragma unroll
    for (int off = 16; off > 0; off >>= 1)
        acc += __shfl_xor_sync(0xFFFFFFFFu, acc, off);

    __shared__ float warp_sums[THREADS / 32];
    const int lane = threadIdx.x & 31;
    const int wid  = threadIdx.x >> 5;
    if (lane == 0) warp_sums[wid] = acc;
    __syncthreads();

    if (wid == 0) {
        float v = (lane < THREADS / 32) ? warp_sums[lane] : 0.0f;
        #pragma unroll
        for (int off = 4; off > 0; off >>= 1)
            v += __shfl_xor_sync(0xFFFFFFFFu, v, off);
        if (lane == 0)
            atomicAdd(out, v);
    }
}

extern "C" void kernel_launch(void* const* d_in, const int* in_sizes, int n_in,
                              void* d_out, int out_size) {
    const float* x = (const float*)d_in[0];
    const float* y = (const float*)d_in[1];
    float* out = (float*)d_out;

    const int total = in_sizes[0];        // B*N*C elements (16,777,216)
    const int n_slots = total / 4;        // one float4 per slot

    mloss_init<<<1, 1>>>(out);
    mloss_kernel<<<BLOCKS, THREADS>>>(x, y, out, n_slots);
}